// round 15
// baseline (speedup 1.0000x reference)
#include <cuda_runtime.h>
#include <cstdint>

// OneDilate: out = 10x10 depthwise box filter of (1-x)*0.5, replicate pad 4.
// x: [32,3,512,512] f32 -> out: [32,3,511,511] f32.
// out = 50 - 0.5 * (sum of 100 raw taps).
//
// Warp-autonomous design: NO smem, NO barriers. Each warp owns a
// 116-col x 64-row output strip. Lane l maintains float4 vertical running
// sums for V columns (strip*116 - 4 + 4l .. +3); the horizontal 10-sum is
// built from the lane's own float4 plus __shfl_down of the next lanes'
// float4s (9 shfl warp-instructions per row). Bottoms are LDG.128 with
// depth-2 prefetch; tops are L1-hot re-reads (9-row lag, ~4.6KB/warp).
// Replicate pad: fully-clamped column quads become broadcast scalar loads.
// All 3840 warps fit on chip at once -> single wave, no quantization.

#define IN_H   512
#define IN_W   512
#define OUT_H  511
#define OUT_W  511
#define PLANES 96
#define SPAN   116        // output columns per warp strip (29 lanes x 4)
#define NSX    5          // ceil(511/116)
#define BAND   64         // output rows per warp unit
#define NBY    8          // ceil(511/64)
#define NT     64         // 2 warps per CTA -> fine-grained placement

#define OUTV(S) fmaf((S), -0.5f, 50.0f)

// Load 4 consecutive V-columns of one input row, with replicate-pad clamp.
// c0 is a multiple of 4. Fully-left/right-clamped quads collapse to one
// broadcast scalar (exactly the pad semantics); in-range quads are LDG.128.
__device__ __forceinline__ float4 ldrow4(const float* __restrict__ rowp, int c0)
{
    if (c0 < 0) {                 // cols c0..c0+3 all < 0 -> all clamp to 0
        float v = rowp[0];
        return make_float4(v, v, v, v);
    }
    if (c0 > IN_W - 4) {          // cols all >= IN_W -> all clamp to IN_W-1
        float v = rowp[IN_W - 1];
        return make_float4(v, v, v, v);
    }
    return *(const float4*)(rowp + c0);
}

__global__ __launch_bounds__(NT)
void onedilate_kernel(const float* __restrict__ x, float* __restrict__ out)
{
    // warp-unit id: u in [0, 5*8*96) ; decode strip-x, band-y, plane
    const int u  = blockIdx.x * (NT / 32) + (threadIdx.x >> 5);
    const int l  = threadIdx.x & 31;
    const int sx = u % NSX;
    const int r5 = u / NSX;
    const int by = r5 & (NBY - 1);
    const int p  = r5 >> 3;

    const float* __restrict__ xp = x   + (size_t)p * IN_H * IN_W;
    float* __restrict__       op = out + (size_t)p * OUT_H * OUT_W;

    const int OX0 = sx * SPAN;
    const int OY0 = by * BAND;
    const int c0  = OX0 - 4 + 4 * l;        // lane's V-column base
    const int jmax = (OUT_H - OY0 < BAND) ? (OUT_H - OY0) : BAND;

    // ---- warm-up: vs = sum of input rows OY0-4 .. OY0+4 (clamped)
    float4 vs = make_float4(0.f, 0.f, 0.f, 0.f);
    #pragma unroll
    for (int k = 0; k < 9; k++) {
        int g = OY0 - 4 + k;
        g = (g < 0) ? 0 : g;                 // top clamp only (OY0+4 < 512)
        float4 a = ldrow4(xp + g * IN_W, c0);
        vs.x += a.x; vs.y += a.y; vs.z += a.z; vs.w += a.w;
    }

    // ---- depth-2 bottom prefetch (rows OY0+5, OY0+6, clamped)
    int rb0 = OY0 + 5; rb0 = (rb0 > IN_H - 1) ? IN_H - 1 : rb0;
    int rb1 = OY0 + 6; rb1 = (rb1 > IN_H - 1) ? IN_H - 1 : rb1;
    float4 bn0 = ldrow4(xp + rb0 * IN_W, c0);
    float4 bn1 = ldrow4(xp + rb1 * IN_W, c0);

    const bool prod = (l < 29);              // lanes 29-31 only feed shuffles
    const int  oxb  = OX0 + 4 * l;

    #pragma unroll 2
    for (int j = 0; j < jmax; j++) {
        const int oy = OY0 + j;

        // issue next-next bottom + this row's top early (latency)
        int rbn = oy + 7; rbn = (rbn > IN_H - 1) ? IN_H - 1 : rbn;
        float4 bnew = ldrow4(xp + rbn * IN_W, c0);
        int rt = oy - 4;  rt = (rt < 0) ? 0 : rt;
        float4 tp = ldrow4(xp + rt * IN_W, c0);   // L1-hot (9-row lag)

        float4 bcur;
        if ((j & 1) == 0) { bcur = bn0; bn0 = bnew; }
        else              { bcur = bn1; bn1 = bnew; }

        // vertical slide: window rows [oy-4 .. oy+5]
        vs.x += bcur.x; vs.y += bcur.y; vs.z += bcur.z; vs.w += bcur.w;

        // gather neighbor vertical sums (all 32 lanes participate)
        float4 n1, n2; float n3x;
        n1.x = __shfl_down_sync(0xffffffffu, vs.x, 1);
        n1.y = __shfl_down_sync(0xffffffffu, vs.y, 1);
        n1.z = __shfl_down_sync(0xffffffffu, vs.z, 1);
        n1.w = __shfl_down_sync(0xffffffffu, vs.w, 1);
        n2.x = __shfl_down_sync(0xffffffffu, vs.x, 2);
        n2.y = __shfl_down_sync(0xffffffffu, vs.y, 2);
        n2.z = __shfl_down_sync(0xffffffffu, vs.z, 2);
        n2.w = __shfl_down_sync(0xffffffffu, vs.w, 2);
        n3x  = __shfl_down_sync(0xffffffffu, vs.x, 3);

        // horizontal sliding 10-sum: out col oxb+i sums V[oxb+i-4 .. oxb+i+5]
        float a4 = (vs.x + vs.y) + (vs.z + vs.w);
        float b4 = (n1.x + n1.y) + (n1.z + n1.w);
        float s0 = a4 + b4 + (n2.x + n2.y);
        float s1 = s0 - vs.x + n2.z;
        float s2 = s1 - vs.y + n2.w;
        float s3 = s2 - vs.z + n3x;

        if (prod) {
            float* __restrict__ orow = op + (size_t)oy * OUT_W;
            if (oxb + 3 < OUT_W) {
                orow[oxb    ] = OUTV(s0);
                orow[oxb + 1] = OUTV(s1);
                orow[oxb + 2] = OUTV(s2);
                orow[oxb + 3] = OUTV(s3);
            } else {
                if (oxb     < OUT_W) orow[oxb    ] = OUTV(s0);
                if (oxb + 1 < OUT_W) orow[oxb + 1] = OUTV(s1);
                if (oxb + 2 < OUT_W) orow[oxb + 2] = OUTV(s2);
            }
        }

        vs.x -= tp.x; vs.y -= tp.y; vs.z -= tp.z; vs.w -= tp.w;
    }
}

extern "C" void kernel_launch(void* const* d_in, const int* in_sizes, int n_in,
                              void* d_out, int out_size)
{
    const float* x = (const float*)d_in[0];
    float* out = (float*)d_out;

    // 5 strips x 8 bands x 96 planes = 3840 warp-units = 1920 CTAs of 64 thr
    const int nblocks = (NSX * NBY * PLANES * 32) / NT;
    onedilate_kernel<<<nblocks, NT>>>(x, out);
}

// round 16
// speedup vs baseline: 1.7902x; 1.7902x over previous
#include <cuda_runtime.h>
#include <cstdint>

// OneDilate: out = 10x10 depthwise box filter of (1-x)*0.5, replicate pad 4.
// x: [32,3,512,512] f32 -> out: [32,3,511,511] f32.
// out = 50 - 0.5 * (sum of 100 raw taps).
//
// R11 (best: 45.6us) byte-identical, single lever: __launch_bounds__(160, 7)
// caps regs 64 -> 58 so 7 CTAs/SM fit (35 warps, 55% theoretical occupancy
// vs 47%). Pure occupancy experiment with the algorithm held fixed:
//  - vertical register history bufA/bufB: 1 LDG/row, top from registers
//  - prefetch next chunk's 16 bottoms before the barrier (MLP=16)
//  - V double-buffered in smem, ONE __syncthreads per chunk
//  - consume: 4 outputs/thread via 4x LDS.128, strided STG.32

#define IN_H   512
#define IN_W   512
#define OUT_H  511
#define OUT_W  511
#define PLANES 96
#define TILE_X 128
#define TILE_Y 128
#define CH     16
#define NCHUNK 8           // TILE_Y / CH
#define VW     137         // TILE_X + 9 vertical columns
#define VSTR   140         // padded row stride (16B aligned, conflict-free)
#define NT     160         // 5 warps

// One pipeline step: produce V rows for chunk CK from CUR (regs), prefetch
// chunk CK+1 into NXT (regs), barrier, consume chunk CK from smem VB.
// top row value: for jj<=8 it was loaded in the previous chunk (NXT[jj+7]
// still holds it), for jj>=9 it is CUR[jj-9]. All indices compile-time.
#define STEP(CK, CUR, NXT, VB) do {                                          \
    const int jb = ty0 + (CK) * CH;                                          \
    if (vrole) {                                                             \
        _Pragma("unroll")                                                    \
        for (int jj = 0; jj < CH; jj++) {                                    \
            float v = CUR[jj];                                               \
            vs += v;                               /* rows [oy-4 .. oy+5] */ \
            VB[jj * VSTR + t] = vs;                                          \
            vs -= (jj <= 8) ? NXT[jj + 7] : CUR[jj - 9];                     \
        }                                                                    \
        if ((CK) < NCHUNK - 1) {                                             \
            _Pragma("unroll")                                                \
            for (int jj = 0; jj < CH; jj++) {                                \
                int g = jb + CH + jj + 5;                                    \
                g = (g > IN_H - 1) ? IN_H - 1 : g;                           \
                NXT[jj] = xc[g * IN_W];                                      \
            }                                                                \
        }                                                                    \
    }                                                                        \
    __syncthreads();                                                         \
    for (int item = t; item < CH * 32; item += NT) {                         \
        const int jj = item >> 5;                                            \
        const int l  = item & 31;                                            \
        const float4* __restrict__ Vv = (const float4*)(VB + jj*VSTR + 4*l); \
        float4 a = Vv[0], b = Vv[1], c4 = Vv[2], d = Vv[3];                  \
        float s0 = ((a.x + a.y) + (a.z + a.w))                               \
                 + ((b.x + b.y) + (b.z + b.w)) + (c4.x + c4.y);              \
        float s1 = s0 - a.x + c4.z;                                          \
        float s2 = s1 - a.y + c4.w;                                          \
        float s3 = s2 - a.z + d.x;                                           \
        const int oy = jb + jj;                                              \
        const int ox = tx0 + 4 * l;                                          \
        if (oy < OUT_H) {                                                    \
            float* __restrict__ o = op + (size_t)oy * OUT_W + ox;            \
            if (ox + 3 < OUT_W) {                                            \
                o[0] = fmaf(s0, -0.5f, 50.0f);                               \
                o[1] = fmaf(s1, -0.5f, 50.0f);                               \
                o[2] = fmaf(s2, -0.5f, 50.0f);                               \
                o[3] = fmaf(s3, -0.5f, 50.0f);                               \
            } else {                                                         \
                if (ox     < OUT_W) o[0] = fmaf(s0, -0.5f, 50.0f);           \
                if (ox + 1 < OUT_W) o[1] = fmaf(s1, -0.5f, 50.0f);           \
                if (ox + 2 < OUT_W) o[2] = fmaf(s2, -0.5f, 50.0f);           \
            }                                                                \
        }                                                                    \
    }                                                                        \
} while (0)

__global__ __launch_bounds__(NT, 7)
void onedilate_kernel(const float* __restrict__ x, float* __restrict__ out)
{
    __shared__ __align__(16) float V[2][CH * VSTR];   // 17,920 B

    const int tx0 = blockIdx.x * TILE_X;
    const int ty0 = blockIdx.y * TILE_Y;
    const int p   = blockIdx.z;
    const float* __restrict__ xp = x   + (size_t)p * IN_H * IN_W;
    float* __restrict__       op = out + (size_t)p * OUT_H * OUT_W;
    const int t = threadIdx.x;

    // vertical role: one input column per thread (clamped = replicate pad)
    int col = tx0 - 4 + t;
    col = (col < 0) ? 0 : (col > IN_W - 1 ? IN_W - 1 : col);
    const float* __restrict__ xc = xp + col;
    const bool vrole = (t < VW);

    float bufA[CH], bufB[CH];
    float vs = 0.0f;

    if (vrole) {
        // warm-up history: rows ty0-4 .. ty0+4 (clamped) -> bufB[7..15]
        #pragma unroll
        for (int k = 0; k < 9; k++) {
            int g = ty0 - 4 + k;
            g = (g < 0) ? 0 : (g > IN_H - 1 ? IN_H - 1 : g);
            bufB[7 + k] = xc[g * IN_W];
            vs += bufB[7 + k];
        }
        // prefetch chunk 0: rows ty0+5 .. ty0+20 (clamped) -> bufA
        #pragma unroll
        for (int jj = 0; jj < CH; jj++) {
            int g = ty0 + 5 + jj;
            g = (g > IN_H - 1) ? IN_H - 1 : g;
            bufA[jj] = xc[g * IN_W];
        }
    }

    float* __restrict__ V0 = &V[0][0];
    float* __restrict__ V1 = &V[1][0];

    // single barrier per chunk: consume(ck) sits between barrier(ck) and
    // barrier(ck+1); produce(ck+2) into the same buffer is after barrier(ck+1).
    for (int ck = 0; ck < NCHUNK; ck += 2) {
        STEP(ck,     bufA, bufB, V0);
        STEP(ck + 1, bufB, bufA, V1);
    }
}

extern "C" void kernel_launch(void* const* d_in, const int* in_sizes, int n_in,
                              void* d_out, int out_size)
{
    const float* x = (const float*)d_in[0];
    float* out = (float*)d_out;

    dim3 grid((OUT_W + TILE_X - 1) / TILE_X,   // 4
              (OUT_H + TILE_Y - 1) / TILE_Y,   // 4
              PLANES);                          // 96 -> 1536 CTAs
    onedilate_kernel<<<grid, NT>>>(x, out);
}

// round 17
// speedup vs baseline: 1.8947x; 1.0584x over previous
#include <cuda_runtime.h>
#include <cstdint>

// OneDilate: out = 10x10 depthwise box filter of (1-x)*0.5, replicate pad 4.
// x: [32,3,512,512] f32 -> out: [32,3,511,511] f32.
// out = 50 - 0.5 * (sum of 100 raw taps).
//
// R11 skeleton (register-history produce, prefetch, 1 barrier/chunk,
// 4-output consume) + per-row aligned stores:
//  - produce writes V row at word shift dp=4-a (a = (4-(p+3*oy))&3 phase),
//    so consume LDS.128 at uniform word 4+4l is 16B-aligned AND the 4-output
//    group lands 16B-aligned in gmem -> ONE STG.128 (4 wavefronts/row vs 16).
//  - tiles abut exactly (a independent of blockIdx.x); the <=3-col right
//    overshoot duplicates the next tile's identical values (VW=140 provides
//    the taps). Left global edge fixed by lane 0 of tx0==0 tiles.

#define IN_H   512
#define IN_W   512
#define OUT_H  511
#define OUT_W  511
#define PLANES 96
#define TILE_X 128
#define TILE_Y 128
#define CH     16
#define NCHUNK 8           // TILE_Y / CH
#define VW     140         // V columns: tx0-4 .. tx0+135 (overshoot taps)
#define VSTR   144         // consume reads words up to 143; %4==0
#define NT     160         // 5 warps

#define OUTV(S) fmaf((S), -0.5f, 50.0f)

// One pipeline step: produce V rows for chunk CK from CUR (regs), prefetch
// chunk CK+1 into NXT (regs), barrier, consume chunk CK from smem VB.
// top value: jj<=8 -> NXT[jj+7] (prev chunk's load), jj>=9 -> CUR[jj-9].
#define STEP(CK, CUR, NXT, VB) do {                                          \
    const int jb = ty0 + (CK) * CH;                                          \
    if (vrole) {                                                             \
        _Pragma("unroll")                                                    \
        for (int jj = 0; jj < CH; jj++) {                                    \
            float v = CUR[jj];                                               \
            vs += v;                               /* rows [oy-4 .. oy+5] */ \
            int dd = (p + 3 * (jb + jj)) & 3;                                \
            int dp = ((dd - 1) & 3) + 1;           /* dp = 4 - a */          \
            VB[jj * VSTR + dp + t] = vs;           /* V col k at word k+dp */\
            vs -= (jj <= 8) ? NXT[jj + 7] : CUR[jj - 9];                     \
        }                                                                    \
        if ((CK) < NCHUNK - 1) {                                             \
            _Pragma("unroll")                                                \
            for (int jj = 0; jj < CH; jj++) {                                \
                int g = jb + CH + jj + 5;                                    \
                g = (g > IN_H - 1) ? IN_H - 1 : g;                           \
                NXT[jj] = xc[g * IN_W];                                      \
            }                                                                \
        }                                                                    \
    }                                                                        \
    __syncthreads();                                                         \
    for (int item = t; item < CH * 32; item += NT) {                         \
        const int jj = item >> 5;                                            \
        const int l  = item & 31;                                            \
        const int oy = jb + jj;                                              \
        if (oy < OUT_H) {                                                    \
            const int dd = (p + 3 * oy) & 3;                                 \
            const int a  = (4 - dd) & 3;                                     \
            const float* __restrict__ row = VB + jj * VSTR;                  \
            const float4* __restrict__ qp = (const float4*)(row + 4 + 4*l);  \
            float4 q0 = qp[0], q1 = qp[1], q2 = qp[2], q3 = qp[3];           \
            /* word 4+4l+i = V col (a+4l+i); out col c sums V[c-4..c+5] */   \
            float s0 = ((q0.x + q0.y) + (q0.z + q0.w))                       \
                     + ((q1.x + q1.y) + (q1.z + q1.w)) + (q2.x + q2.y);      \
            float s1 = s0 - q0.x + q2.z;                                     \
            float s2 = s1 - q0.y + q2.w;                                     \
            float s3 = s2 - q0.z + q3.x;                                     \
            float* __restrict__ orow = op + (size_t)oy * OUT_W;              \
            const int ox = tx0 + a + 4 * l;        /* 16B-aligned */         \
            if (ox + 3 < OUT_W) {                                            \
                *(float4*)(orow + ox) =                                      \
                    make_float4(OUTV(s0), OUTV(s1), OUTV(s2), OUTV(s3));     \
            } else {                                                         \
                if (ox     < OUT_W) orow[ox]     = OUTV(s0);                 \
                if (ox + 1 < OUT_W) orow[ox + 1] = OUTV(s1);                 \
                if (ox + 2 < OUT_W) orow[ox + 2] = OUTV(s2);                 \
                if (ox + 3 < OUT_W) orow[ox + 3] = OUTV(s3);                 \
            }                                                                \
            if (tx0 == 0 && l == 0 && a > 0) {                               \
                /* global left edge cols 0..a-1, slide left from s0 */       \
                float4 m = *(const float4*)row;    /* words 0..3 */          \
                float sv = s0 - q2.y + m.w;        /* col a-1 */             \
                orow[a - 1] = OUTV(sv);                                      \
                if (a > 1) { sv = sv - q2.x + m.z; orow[a - 2] = OUTV(sv); } \
                if (a > 2) { sv = sv - q1.w + m.y; orow[a - 3] = OUTV(sv); } \
            }                                                                \
        }                                                                    \
    }                                                                        \
} while (0)

__global__ __launch_bounds__(NT)
void onedilate_kernel(const float* __restrict__ x, float* __restrict__ out)
{
    __shared__ __align__(16) float V[2][CH * VSTR];   // 18,432 B

    const int tx0 = blockIdx.x * TILE_X;
    const int ty0 = blockIdx.y * TILE_Y;
    const int p   = blockIdx.z;
    const float* __restrict__ xp = x   + (size_t)p * IN_H * IN_W;
    float* __restrict__       op = out + (size_t)p * OUT_H * OUT_W;
    const int t = threadIdx.x;

    // vertical role: one input column per thread (clamped = replicate pad)
    int col = tx0 - 4 + t;
    col = (col < 0) ? 0 : (col > IN_W - 1 ? IN_W - 1 : col);
    const float* __restrict__ xc = xp + col;
    const bool vrole = (t < VW);

    float bufA[CH], bufB[CH];
    float vs = 0.0f;

    if (vrole) {
        // warm-up history: rows ty0-4 .. ty0+4 (clamped) -> bufB[7..15]
        #pragma unroll
        for (int k = 0; k < 9; k++) {
            int g = ty0 - 4 + k;
            g = (g < 0) ? 0 : (g > IN_H - 1 ? IN_H - 1 : g);
            bufB[7 + k] = xc[g * IN_W];
            vs += bufB[7 + k];
        }
        // prefetch chunk 0: rows ty0+5 .. ty0+20 (clamped) -> bufA
        #pragma unroll
        for (int jj = 0; jj < CH; jj++) {
            int g = ty0 + 5 + jj;
            g = (g > IN_H - 1) ? IN_H - 1 : g;
            bufA[jj] = xc[g * IN_W];
        }
    }

    float* __restrict__ V0 = &V[0][0];
    float* __restrict__ V1 = &V[1][0];

    // single barrier per chunk: consume(ck) sits between barrier(ck) and
    // barrier(ck+1); produce(ck+2) into the same buffer is after barrier(ck+1).
    for (int ck = 0; ck < NCHUNK; ck += 2) {
        STEP(ck,     bufA, bufB, V0);
        STEP(ck + 1, bufB, bufA, V1);
    }
}

extern "C" void kernel_launch(void* const* d_in, const int* in_sizes, int n_in,
                              void* d_out, int out_size)
{
    const float* x = (const float*)d_in[0];
    float* out = (float*)d_out;

    dim3 grid((OUT_W + TILE_X - 1) / TILE_X,   // 4
              (OUT_H + TILE_Y - 1) / TILE_Y,   // 4
              PLANES);                          // 96 -> 1536 CTAs
    onedilate_kernel<<<grid, NT>>>(x, out);
}